// round 2
// baseline (speedup 1.0000x reference)
#include <cuda_runtime.h>
#include <cstdint>
#include <cstddef>

#define LRELU(v) ((v) >= 0.f ? (v) : 0.01f * (v))

static __device__ __forceinline__ void fma2(unsigned long long& acc,
                                            unsigned long long w,
                                            unsigned long long v) {
    asm("fma.rn.f32x2 %0, %1, %2, %0;" : "+l"(acc) : "l"(w), "l"(v));
}
static __device__ __forceinline__ unsigned long long pack2(float v) {
    unsigned long long r;
    asm("mov.b64 %0, {%1, %1};" : "=l"(r) : "f"(v));
    return r;
}
static __device__ __forceinline__ float lo32(unsigned long long a) {
    return __uint_as_float((unsigned)(a & 0xffffffffull));
}
static __device__ __forceinline__ float hi32(unsigned long long a) {
    return __uint_as_float((unsigned)(a >> 32));
}

__device__ __align__(16) float g_bufA[33554432];
__device__ __align__(16) float g_bufB[33554432];
__device__ __align__(16) float g_wT[22009536];
__device__ float g_mean[1024];
__device__ float g_invstd[1024];

#define OFF_D0 0
#define OFF_D1 1728
#define OFF_D2 75456
#define OFF_D3 370368
#define OFF_D4 1550016
#define OFF_IN 6268608
#define OFF_U0 15705792
#define OFF_U1 20424384
#define OFF_U2 21604032
#define OFF_U3 21898944
#define OFF_U4 21972672

// src [R=CO][C=CI*9] -> dst [C][R]
__global__ void wtrans_kernel(const float* __restrict__ src, float* __restrict__ dst,
                              int R, int C) {
    __shared__ float t[32][33];
    int bc = blockIdx.x * 32, br = blockIdx.y * 32;
    int x = threadIdx.x, y = threadIdx.y;
    #pragma unroll
    for (int j = 0; j < 32; j += 8) {
        int r = br + y + j, c = bc + x;
        if (r < R && c < C) t[y + j][x] = src[(size_t)r * C + c];
    }
    __syncthreads();
    #pragma unroll
    for (int j = 0; j < 32; j += 8) {
        int c = bc + y + j, r = br + x;
        if (r < R && c < C) dst[(size_t)c * R + r] = t[x][y + j];
    }
}

__global__ void zero_kernel(float* __restrict__ p, int n) {
    int i = blockIdx.x * 256 + threadIdx.x;
    if (i < n) p[i] = 0.f;
}

__global__ void bias_lrelu_kernel(float* __restrict__ p, const float* __restrict__ b,
                                  int HW, int C, int total) {
    int i = blockIdx.x * 256 + threadIdx.x;
    if (i < total) {
        int c = (i / HW) % C;
        float v = p[i] + b[c];
        p[i] = LRELU(v);
    }
}

// ---------------- encoder / plain conv (S=2 fused subsample) ----------------
template <int CI, int CO, int HO, int WO, int S, int CICH, int SPLIT, bool FUSE>
__global__ __launch_bounds__(256, 2)
void conv_enc(const float* __restrict__ in, const float* __restrict__ wT,
              const float* __restrict__ bias, float* __restrict__ out) {
    constexpr int TH = 8, TW = 16, TCO = 64;
    constexpr int HIN = HO * S, WIN = WO * S;
    constexpr int TILESX = WO / TW;
    constexpr int COT = CO / TCO;
    constexpr int PH = S * TH + 3 - S, PW = S * TW + 3 - S;
    constexpr int CIS = CI / SPLIT;

    __shared__ __align__(16) float s_in[CICH][PH][PW];
    __shared__ __align__(16) float s_w[CICH][9][TCO];

    const int tid = threadIdx.x;
    const int px_id = tid & 31;
    const int co_grp = tid >> 5;
    const int n = blockIdx.y / COT;
    const int cot = blockIdx.y % COT;
    const int ty = blockIdx.x / TILESX;
    const int tx = blockIdx.x % TILESX;
    const int co0 = cot * TCO;
    const int oy0 = ty * TH, ox0 = tx * TW;
    const int iy0 = S * oy0 - 1, ix0 = S * ox0 - 1;
    const int ci_beg = CIS * blockIdx.z;

    unsigned long long acc[4][4];
    #pragma unroll
    for (int p = 0; p < 4; p++)
        #pragma unroll
        for (int k = 0; k < 4; k++) acc[p][k] = 0ull;

    for (int cc = 0; cc < CIS; cc += CICH) {
        const int ci0 = ci_beg + cc;
        #pragma unroll 1
        for (int idx = tid; idx < CICH * PH * PW; idx += 256) {
            int ci = idx / (PH * PW);
            int rem = idx - ci * (PH * PW);
            int r = rem / PW, c = rem - r * PW;
            int gy = iy0 + r, gx = ix0 + c;
            float v = 0.f;
            if (gy >= 0 && gy < HIN && gx >= 0 && gx < WIN)
                v = in[(((size_t)n * CI + ci0 + ci) * HIN + gy) * WIN + gx];
            s_in[ci][r][c] = v;
        }
        #pragma unroll 1
        for (int idx = tid; idx < CICH * 9 * (TCO / 4); idx += 256) {
            int row = idx / (TCO / 4);
            int c4 = idx - row * (TCO / 4);
            int ci = row / 9, tap = row - ci * 9;
            float4 v = *(const float4*)&wT[((size_t)(ci0 + ci) * 9 + tap) * CO + co0 + c4 * 4];
            *(float4*)&s_w[ci][tap][c4 * 4] = v;
        }
        __syncthreads();
        #pragma unroll 1
        for (int ci = 0; ci < CICH; ci++) {
            #pragma unroll
            for (int tap = 0; tap < 9; tap++) {
                const int ky = tap / 3, kx = tap % 3;
                ulonglong2 wa = *(const ulonglong2*)&s_w[ci][tap][co_grp * 8];
                ulonglong2 wb = *(const ulonglong2*)&s_w[ci][tap][co_grp * 8 + 4];
                #pragma unroll
                for (int k = 0; k < 4; k++) {
                    const int cell = px_id + k * 32;
                    const int cy = cell / TW, cx = cell % TW;
                    unsigned long long vv = pack2(s_in[ci][S * cy + ky][S * cx + kx]);
                    fma2(acc[0][k], wa.x, vv);
                    fma2(acc[1][k], wa.y, vv);
                    fma2(acc[2][k], wb.x, vv);
                    fma2(acc[3][k], wb.y, vv);
                }
            }
        }
        __syncthreads();
    }

    #pragma unroll
    for (int p = 0; p < 4; p++) {
        const int co = co0 + co_grp * 8 + 2 * p;
        #pragma unroll
        for (int k = 0; k < 4; k++) {
            const int cell = px_id + k * 32;
            const int cy = cell / TW, cx = cell % TW;
            const size_t idx = (((size_t)n * CO + co) * HO + oy0 + cy) * WO + ox0 + cx;
            float v0 = lo32(acc[p][k]), v1 = hi32(acc[p][k]);
            if constexpr (FUSE) {
                v0 += bias[co]; v1 += bias[co + 1];
                out[idx] = LRELU(v0);
                out[idx + (size_t)HO * WO] = LRELU(v1);
            } else {
                atomicAdd(&out[idx], v0);
                atomicAdd(&out[idx + (size_t)HO * WO], v1);
            }
        }
    }
}

// ---------------- decoder: zero-insert up2 + conv3x3 ----------------
template <int CI, int CO, int HIN, int WIN, int CICH, int SPLIT, bool FUSE>
__global__ __launch_bounds__(256)
void conv_dec(const float* __restrict__ in, const float* __restrict__ wT,
              const float* __restrict__ bias, float* __restrict__ out) {
    constexpr int TH = 8, TW = 8, TCO = 64;
    constexpr int HOUT = 2 * HIN, WOUT = 2 * WIN;
    constexpr int TILESX = WIN / TW;
    constexpr int COT = CO / TCO;
    constexpr int PH = TH + 1, PW = TW + 1;
    constexpr int CIS = CI / SPLIT;

    __shared__ __align__(16) float s_in[CICH][PH][PW];
    __shared__ __align__(16) float s_w[CICH][9][TCO];

    const int tid = threadIdx.x;
    const int px_id = tid & 31;
    const int co_grp = tid >> 5;
    const int n = blockIdx.y / COT;
    const int cot = blockIdx.y % COT;
    const int ty = blockIdx.x / TILESX;
    const int tx = blockIdx.x % TILESX;
    const int co0 = cot * TCO;
    const int i0 = ty * TH, j0 = tx * TW;
    const int ci_beg = CIS * blockIdx.z;

    unsigned long long acc[4][2][4];
    #pragma unroll
    for (int p = 0; p < 4; p++)
        #pragma unroll
        for (int k = 0; k < 2; k++)
            #pragma unroll
            for (int q = 0; q < 4; q++) acc[p][k][q] = 0ull;

    // tap (ky,kx) rowmajor -> output parity q=2a+b (a=ky!=1, b=kx!=1),
    // input from (i + (ky==2), j + (kx==2))
    constexpr int OUTI[9] = {3, 2, 3, 1, 0, 1, 3, 2, 3};
    constexpr int VI[9]   = {0, 0, 1, 0, 0, 1, 2, 2, 3};

    for (int cc = 0; cc < CIS; cc += CICH) {
        const int ci0 = ci_beg + cc;
        #pragma unroll 1
        for (int idx = tid; idx < CICH * PH * PW; idx += 256) {
            int ci = idx / (PH * PW);
            int rem = idx - ci * (PH * PW);
            int r = rem / PW, c = rem - r * PW;
            int gy = i0 + r, gx = j0 + c;
            float v = 0.f;
            if (gy < HIN && gx < WIN)
                v = in[(((size_t)n * CI + ci0 + ci) * HIN + gy) * WIN + gx];
            s_in[ci][r][c] = v;
        }
        #pragma unroll 1
        for (int idx = tid; idx < CICH * 9 * (TCO / 4); idx += 256) {
            int row = idx / (TCO / 4);
            int c4 = idx - row * (TCO / 4);
            int ci = row / 9, tap = row - ci * 9;
            float4 v = *(const float4*)&wT[((size_t)(ci0 + ci) * 9 + tap) * CO + co0 + c4 * 4];
            *(float4*)&s_w[ci][tap][c4 * 4] = v;
        }
        __syncthreads();
        #pragma unroll 1
        for (int ci = 0; ci < CICH; ci++) {
            unsigned long long vv[2][4];
            #pragma unroll
            for (int k = 0; k < 2; k++) {
                const int cell = px_id + k * 32;
                const int cy = cell / TW, cx = cell % TW;
                vv[k][0] = pack2(s_in[ci][cy][cx]);
                vv[k][1] = pack2(s_in[ci][cy][cx + 1]);
                vv[k][2] = pack2(s_in[ci][cy + 1][cx]);
                vv[k][3] = pack2(s_in[ci][cy + 1][cx + 1]);
            }
            #pragma unroll
            for (int tap = 0; tap < 9; tap++) {
                ulonglong2 wa = *(const ulonglong2*)&s_w[ci][tap][co_grp * 8];
                ulonglong2 wb = *(const ulonglong2*)&s_w[ci][tap][co_grp * 8 + 4];
                const int q = OUTI[tap], vi = VI[tap];
                #pragma unroll
                for (int k = 0; k < 2; k++) {
                    fma2(acc[0][k][q], wa.x, vv[k][vi]);
                    fma2(acc[1][k][q], wa.y, vv[k][vi]);
                    fma2(acc[2][k][q], wb.x, vv[k][vi]);
                    fma2(acc[3][k][q], wb.y, vv[k][vi]);
                }
            }
        }
        __syncthreads();
    }

    #pragma unroll
    for (int p = 0; p < 4; p++) {
        const int co = co0 + co_grp * 8 + 2 * p;
        #pragma unroll
        for (int k = 0; k < 2; k++) {
            const int cell = px_id + k * 32;
            const int gi = i0 + cell / TW, gj = j0 + cell % TW;
            const size_t base = (((size_t)n * CO + co) * HOUT + 2 * gi) * WOUT + 2 * gj;
            const size_t plane = (size_t)HOUT * WOUT;
            const size_t offs[4] = {0, 1, (size_t)WOUT, (size_t)WOUT + 1};
            #pragma unroll
            for (int q = 0; q < 4; q++) {
                float v0 = lo32(acc[p][k][q]), v1 = hi32(acc[p][k][q]);
                if constexpr (FUSE) {
                    v0 += bias[co]; v1 += bias[co + 1];
                    out[base + offs[q]] = LRELU(v0);
                    out[base + offs[q] + plane] = LRELU(v1);
                } else {
                    atomicAdd(&out[base + offs[q]], v0);
                    atomicAdd(&out[base + offs[q] + plane], v1);
                }
            }
        }
    }
}

// ---------------- batchnorm on [2][1024][16][16] ----------------
__global__ void bn_stats_kernel(const float* __restrict__ h) {
    __shared__ float ssum[256], ssq[256];
    int c = blockIdx.x, tid = threadIdx.x;
    float v0 = h[((size_t)0 * 1024 + c) * 256 + tid];
    float v1 = h[((size_t)1 * 1024 + c) * 256 + tid];
    ssum[tid] = v0 + v1;
    ssq[tid] = v0 * v0 + v1 * v1;
    __syncthreads();
    for (int o = 128; o > 0; o >>= 1) {
        if (tid < o) { ssum[tid] += ssum[tid + o]; ssq[tid] += ssq[tid + o]; }
        __syncthreads();
    }
    if (tid == 0) {
        float m = ssum[0] * (1.f / 512.f);
        float var = ssq[0] * (1.f / 512.f) - m * m;
        g_mean[c] = m;
        g_invstd[c] = rsqrtf(var + 1e-5f);
    }
}

__global__ void bn_apply_kernel(float* __restrict__ h, const float* __restrict__ gamma,
                                const float* __restrict__ beta) {
    int i = blockIdx.x * 256 + threadIdx.x;
    int c = (i >> 8) & 1023;
    float v = (h[i] - g_mean[c]) * g_invstd[c] * gamma[c] + beta[c];
    h[i] = LRELU(v);
}

// ---------------- epilogue 1x1 conv 64->3 ----------------
__global__ void ep_kernel(const float* __restrict__ in, const float* __restrict__ wep,
                          const float* __restrict__ bep, float* __restrict__ out) {
    __shared__ float sw[3][64];
    __shared__ float sb[3];
    int tid = threadIdx.x;
    if (tid < 192) sw[tid / 64][tid % 64] = wep[tid];
    if (tid < 3) sb[tid] = bep[tid];
    __syncthreads();
    size_t px = (size_t)blockIdx.x * 256 + tid;
    int n = (int)(px >> 18);
    int hw = (int)(px & 262143);
    const float* base = in + ((size_t)n * 64) * 262144 + hw;
    float a0 = sb[0], a1 = sb[1], a2 = sb[2];
    #pragma unroll 8
    for (int c = 0; c < 64; c++) {
        float v = base[(size_t)c * 262144];
        a0 += sw[0][c] * v;
        a1 += sw[1][c] * v;
        a2 += sw[2][c] * v;
    }
    out[((size_t)n * 3 + 0) * 262144 + hw] = a0;
    out[((size_t)n * 3 + 1) * 262144 + hw] = a1;
    out[((size_t)n * 3 + 2) * 262144 + hw] = a2;
}

extern "C" void kernel_launch(void* const* d_in, const int* in_sizes, int n_in,
                              void* d_out, int out_size) {
    (void)in_sizes; (void)n_in; (void)out_size;
    float *bufA, *bufB, *wT;
    cudaGetSymbolAddress((void**)&bufA, g_bufA);
    cudaGetSymbolAddress((void**)&bufB, g_bufB);
    cudaGetSymbolAddress((void**)&wT, g_wT);

    const float* x    = (const float*)d_in[0];
    const float* w_d0 = (const float*)d_in[1];
    const float* b_d0 = (const float*)d_in[2];
    const float* w_d1 = (const float*)d_in[3];
    const float* b_d1 = (const float*)d_in[4];
    const float* w_d2 = (const float*)d_in[5];
    const float* b_d2 = (const float*)d_in[6];
    const float* w_d3 = (const float*)d_in[7];
    const float* b_d3 = (const float*)d_in[8];
    const float* w_d4 = (const float*)d_in[9];
    const float* b_d4 = (const float*)d_in[10];
    const float* w_in = (const float*)d_in[11];
    const float* gamma = (const float*)d_in[13];
    const float* beta  = (const float*)d_in[14];
    const float* w_u0 = (const float*)d_in[15];
    const float* b_u0 = (const float*)d_in[16];
    const float* w_u1 = (const float*)d_in[17];
    const float* b_u1 = (const float*)d_in[18];
    const float* w_u2 = (const float*)d_in[19];
    const float* b_u2 = (const float*)d_in[20];
    const float* w_u3 = (const float*)d_in[21];
    const float* b_u3 = (const float*)d_in[22];
    const float* w_u4 = (const float*)d_in[23];
    const float* b_u4 = (const float*)d_in[24];
    const float* w_ep = (const float*)d_in[25];
    const float* b_ep = (const float*)d_in[26];

    dim3 tb(32, 8);
    auto tg = [](int C, int R) { return dim3((unsigned)((C + 31) / 32), (unsigned)((R + 31) / 32)); };
    wtrans_kernel<<<tg(27, 64), tb>>>(w_d0, wT + OFF_D0, 64, 27);
    wtrans_kernel<<<tg(576, 128), tb>>>(w_d1, wT + OFF_D1, 128, 576);
    wtrans_kernel<<<tg(1152, 256), tb>>>(w_d2, wT + OFF_D2, 256, 1152);
    wtrans_kernel<<<tg(2304, 512), tb>>>(w_d3, wT + OFF_D3, 512, 2304);
    wtrans_kernel<<<tg(4608, 1024), tb>>>(w_d4, wT + OFF_D4, 1024, 4608);
    wtrans_kernel<<<tg(9216, 1024), tb>>>(w_in, wT + OFF_IN, 1024, 9216);
    wtrans_kernel<<<tg(9216, 512), tb>>>(w_u0, wT + OFF_U0, 512, 9216);
    wtrans_kernel<<<tg(4608, 256), tb>>>(w_u1, wT + OFF_U1, 256, 4608);
    wtrans_kernel<<<tg(2304, 128), tb>>>(w_u2, wT + OFF_U2, 128, 2304);
    wtrans_kernel<<<tg(1152, 64), tb>>>(w_u3, wT + OFF_U3, 64, 1152);
    wtrans_kernel<<<tg(576, 64), tb>>>(w_u4, wT + OFF_U4, 64, 576);

    // encoder
    conv_enc<3, 64, 256, 256, 2, 3, 1, true><<<dim3(512, 2, 1), 256>>>(x, wT + OFF_D0, b_d0, bufA);
    conv_enc<64, 128, 128, 128, 2, 8, 1, true><<<dim3(128, 4, 1), 256>>>(bufA, wT + OFF_D1, b_d1, bufB);
    conv_enc<128, 256, 64, 64, 2, 8, 1, true><<<dim3(32, 8, 1), 256>>>(bufB, wT + OFF_D2, b_d2, bufA);

    zero_kernel<<<4096, 256>>>(bufB, 1048576);
    conv_enc<256, 512, 32, 32, 2, 8, 2, false><<<dim3(8, 16, 2), 256>>>(bufA, wT + OFF_D3, nullptr, bufB);
    bias_lrelu_kernel<<<4096, 256>>>(bufB, b_d3, 1024, 512, 1048576);

    zero_kernel<<<2048, 256>>>(bufA, 524288);
    conv_enc<512, 1024, 16, 16, 2, 8, 4, false><<<dim3(2, 32, 4), 256>>>(bufB, wT + OFF_D4, nullptr, bufA);
    bias_lrelu_kernel<<<2048, 256>>>(bufA, b_d4, 256, 1024, 524288);

    // inner conv + BN + lrelu (conv bias cancels through BN)
    zero_kernel<<<2048, 256>>>(bufB, 524288);
    conv_enc<1024, 1024, 16, 16, 1, 8, 4, false><<<dim3(2, 32, 4), 256>>>(bufA, wT + OFF_IN, nullptr, bufB);
    bn_stats_kernel<<<1024, 256>>>(bufB);
    bn_apply_kernel<<<2048, 256>>>(bufB, gamma, beta);

    // decoder
    zero_kernel<<<4096, 256>>>(bufA, 1048576);
    conv_dec<1024, 512, 16, 16, 8, 4, false><<<dim3(4, 16, 4), 256>>>(bufB, wT + OFF_U0, nullptr, bufA);
    bias_lrelu_kernel<<<4096, 256>>>(bufA, b_u0, 1024, 512, 1048576);

    zero_kernel<<<8192, 256>>>(bufB, 2097152);
    conv_dec<512, 256, 32, 32, 8, 2, false><<<dim3(16, 8, 2), 256>>>(bufA, wT + OFF_U1, nullptr, bufB);
    bias_lrelu_kernel<<<8192, 256>>>(bufB, b_u1, 4096, 256, 2097152);

    conv_dec<256, 128, 64, 64, 8, 1, true><<<dim3(64, 4, 1), 256>>>(bufB, wT + OFF_U2, b_u2, bufA);
    conv_dec<128, 64, 128, 128, 8, 1, true><<<dim3(256, 2, 1), 256>>>(bufA, wT + OFF_U3, b_u3, bufB);
    conv_dec<64, 64, 256, 256, 8, 1, true><<<dim3(1024, 2, 1), 256>>>(bufB, wT + OFF_U4, b_u4, bufA);

    // epilogue
    ep_kernel<<<2048, 256>>>(bufA, w_ep, b_ep, (float*)d_out);
}

// round 4
// speedup vs baseline: 1.0108x; 1.0108x over previous
#include <cuda_runtime.h>
#include <cstdint>
#include <cstddef>

#define LRELU(v) ((v) >= 0.f ? (v) : 0.01f * (v))

static __device__ __forceinline__ void fma2(unsigned long long& acc,
                                            unsigned long long w,
                                            unsigned long long v) {
    asm("fma.rn.f32x2 %0, %1, %2, %0;" : "+l"(acc) : "l"(w), "l"(v));
}
static __device__ __forceinline__ unsigned long long pack2(float v) {
    unsigned long long r;
    asm("mov.b64 %0, {%1, %1};" : "=l"(r) : "f"(v));
    return r;
}
static __device__ __forceinline__ float lo32(unsigned long long a) {
    return __uint_as_float((unsigned)(a & 0xffffffffull));
}
static __device__ __forceinline__ float hi32(unsigned long long a) {
    return __uint_as_float((unsigned)(a >> 32));
}

__device__ __align__(16) float g_bufA[33554432];
__device__ __align__(16) float g_bufB[33554432];
__device__ __align__(16) float g_wT[22009536];
__device__ float g_mean[1024];
__device__ float g_invstd[1024];

#define OFF_D0 0
#define OFF_D1 1728
#define OFF_D2 75456
#define OFF_D3 370368
#define OFF_D4 1550016
#define OFF_IN 6268608
#define OFF_U0 15705792
#define OFF_U1 20424384
#define OFF_U2 21604032
#define OFF_U3 21898944
#define OFF_U4 21972672

// load-time transforms applied to the consumer's input
#define M_NONE 0
#define M_BIAS 1   // lrelu(v + lb[c])
#define M_BN   2   // lrelu((v-mean)*invstd*gamma + beta)

// src [R=CO][C=CI*9] -> dst [C][R]
__global__ void wtrans_kernel(const float* __restrict__ src, float* __restrict__ dst,
                              int R, int C) {
    __shared__ float t[32][33];
    int bc = blockIdx.x * 32, br = blockIdx.y * 32;
    int x = threadIdx.x, y = threadIdx.y;
    #pragma unroll
    for (int j = 0; j < 32; j += 8) {
        int r = br + y + j, c = bc + x;
        if (r < R && c < C) t[y + j][x] = src[(size_t)r * C + c];
    }
    __syncthreads();
    #pragma unroll
    for (int j = 0; j < 32; j += 8) {
        int c = bc + y + j, r = br + x;
        if (r < R && c < C) dst[(size_t)c * R + r] = t[x][y + j];
    }
}

__global__ void zero_kernel(float* __restrict__ p, int n) {
    int i = blockIdx.x * 256 + threadIdx.x;
    if (i < n) p[i] = 0.f;
}

template <int MODE>
static __device__ __forceinline__ float xform(float v, int c, const float* lb,
                                              const float* gamma, const float* beta) {
    if (MODE == M_BIAS) {
        v += lb[c];
        v = LRELU(v);
    } else if (MODE == M_BN) {
        v = (v - g_mean[c]) * g_invstd[c] * gamma[c] + beta[c];
        v = LRELU(v);
    }
    return v;
}

// ---------------- encoder / plain conv (S=2 fused subsample) ----------------
template <int CI, int CO, int HO, int WO, int S, int CICH, int SPLIT, bool FUSE, int MODE>
__global__ __launch_bounds__(256, 2)
void conv_enc(const float* __restrict__ in, const float* __restrict__ wT,
              const float* __restrict__ bias, const float* __restrict__ lb,
              const float* __restrict__ gamma, const float* __restrict__ beta,
              float* __restrict__ out) {
    constexpr int TH = 8, TW = 16, TCO = 64;
    constexpr int HIN = HO * S, WIN = WO * S;
    constexpr int TILESX = WO / TW;
    constexpr int COT = CO / TCO;
    constexpr int PH = S * TH + 3 - S, PW = S * TW + 3 - S;
    constexpr int CIS = CI / SPLIT;

    __shared__ __align__(16) float s_in[CICH][PH][PW];
    __shared__ __align__(16) float s_w[CICH][9][TCO];

    const int tid = threadIdx.x;
    const int px_id = tid & 31;
    const int co_grp = tid >> 5;
    const int n = blockIdx.y / COT;
    const int cot = blockIdx.y % COT;
    const int ty = blockIdx.x / TILESX;
    const int tx = blockIdx.x % TILESX;
    const int co0 = cot * TCO;
    const int oy0 = ty * TH, ox0 = tx * TW;
    const int iy0 = S * oy0 - 1, ix0 = S * ox0 - 1;
    const int ci_beg = CIS * blockIdx.z;

    unsigned long long acc[4][4];
    #pragma unroll
    for (int p = 0; p < 4; p++)
        #pragma unroll
        for (int k = 0; k < 4; k++) acc[p][k] = 0ull;

    for (int cc = 0; cc < CIS; cc += CICH) {
        const int ci0 = ci_beg + cc;
        #pragma unroll 1
        for (int idx = tid; idx < CICH * PH * PW; idx += 256) {
            int ci = idx / (PH * PW);
            int rem = idx - ci * (PH * PW);
            int r = rem / PW, c = rem - r * PW;
            int gy = iy0 + r, gx = ix0 + c;
            float v = 0.f;
            if (gy >= 0 && gy < HIN && gx >= 0 && gx < WIN) {
                v = in[(((size_t)n * CI + ci0 + ci) * HIN + gy) * WIN + gx];
                v = xform<MODE>(v, ci0 + ci, lb, gamma, beta);
            }
            s_in[ci][r][c] = v;
        }
        #pragma unroll 1
        for (int idx = tid; idx < CICH * 9 * (TCO / 4); idx += 256) {
            int row = idx / (TCO / 4);
            int c4 = idx - row * (TCO / 4);
            int ci = row / 9, tap = row - ci * 9;
            float4 v = *(const float4*)&wT[((size_t)(ci0 + ci) * 9 + tap) * CO + co0 + c4 * 4];
            *(float4*)&s_w[ci][tap][c4 * 4] = v;
        }
        __syncthreads();
        #pragma unroll 1
        for (int ci = 0; ci < CICH; ci++) {
            #pragma unroll
            for (int tap = 0; tap < 9; tap++) {
                const int ky = tap / 3, kx = tap % 3;
                ulonglong2 wa = *(const ulonglong2*)&s_w[ci][tap][co_grp * 8];
                ulonglong2 wb = *(const ulonglong2*)&s_w[ci][tap][co_grp * 8 + 4];
                #pragma unroll
                for (int k = 0; k < 4; k++) {
                    const int cell = px_id + k * 32;
                    const int cy = cell / TW, cx = cell % TW;
                    unsigned long long vv = pack2(s_in[ci][S * cy + ky][S * cx + kx]);
                    fma2(acc[0][k], wa.x, vv);
                    fma2(acc[1][k], wa.y, vv);
                    fma2(acc[2][k], wb.x, vv);
                    fma2(acc[3][k], wb.y, vv);
                }
            }
        }
        __syncthreads();
    }

    #pragma unroll
    for (int p = 0; p < 4; p++) {
        const int co = co0 + co_grp * 8 + 2 * p;
        #pragma unroll
        for (int k = 0; k < 4; k++) {
            const int cell = px_id + k * 32;
            const int cy = cell / TW, cx = cell % TW;
            const size_t idx = (((size_t)n * CO + co) * HO + oy0 + cy) * WO + ox0 + cx;
            float v0 = lo32(acc[p][k]), v1 = hi32(acc[p][k]);
            if constexpr (FUSE) {
                v0 += bias[co]; v1 += bias[co + 1];
                out[idx] = LRELU(v0);
                out[idx + (size_t)HO * WO] = LRELU(v1);
            } else {
                atomicAdd(&out[idx], v0);
                atomicAdd(&out[idx + (size_t)HO * WO], v1);
            }
        }
    }
}

// ---------------- decoder: zero-insert up2 + conv3x3 ----------------
template <int CI, int CO, int HIN, int WIN, int CICH, int SPLIT, bool FUSE, int MODE>
__global__ __launch_bounds__(256, 2)
void conv_dec(const float* __restrict__ in, const float* __restrict__ wT,
              const float* __restrict__ bias, const float* __restrict__ lb,
              const float* __restrict__ gamma, const float* __restrict__ beta,
              float* __restrict__ out) {
    constexpr int TH = 8, TW = 8, TCO = 64;
    constexpr int HOUT = 2 * HIN, WOUT = 2 * WIN;
    constexpr int TILESX = WIN / TW;
    constexpr int COT = CO / TCO;
    constexpr int PH = TH + 1, PW = TW + 1;
    constexpr int CIS = CI / SPLIT;

    __shared__ __align__(16) float s_in[CICH][PH][PW];
    __shared__ __align__(16) float s_w[CICH][9][TCO];

    const int tid = threadIdx.x;
    const int px_id = tid & 31;
    const int co_grp = tid >> 5;
    const int n = blockIdx.y / COT;
    const int cot = blockIdx.y % COT;
    const int ty = blockIdx.x / TILESX;
    const int tx = blockIdx.x % TILESX;
    const int co0 = cot * TCO;
    const int i0 = ty * TH, j0 = tx * TW;
    const int ci_beg = CIS * blockIdx.z;

    unsigned long long acc[4][2][4];
    #pragma unroll
    for (int p = 0; p < 4; p++)
        #pragma unroll
        for (int k = 0; k < 2; k++)
            #pragma unroll
            for (int q = 0; q < 4; q++) acc[p][k][q] = 0ull;

    constexpr int OUTI[9] = {3, 2, 3, 1, 0, 1, 3, 2, 3};
    constexpr int VI[9]   = {0, 0, 1, 0, 0, 1, 2, 2, 3};

    for (int cc = 0; cc < CIS; cc += CICH) {
        const int ci0 = ci_beg + cc;
        #pragma unroll 1
        for (int idx = tid; idx < CICH * PH * PW; idx += 256) {
            int ci = idx / (PH * PW);
            int rem = idx - ci * (PH * PW);
            int r = rem / PW, c = rem - r * PW;
            int gy = i0 + r, gx = j0 + c;
            float v = 0.f;
            if (gy < HIN && gx < WIN) {
                v = in[(((size_t)n * CI + ci0 + ci) * HIN + gy) * WIN + gx];
                v = xform<MODE>(v, ci0 + ci, lb, gamma, beta);
            }
            s_in[ci][r][c] = v;
        }
        #pragma unroll 1
        for (int idx = tid; idx < CICH * 9 * (TCO / 4); idx += 256) {
            int row = idx / (TCO / 4);
            int c4 = idx - row * (TCO / 4);
            int ci = row / 9, tap = row - ci * 9;
            float4 v = *(const float4*)&wT[((size_t)(ci0 + ci) * 9 + tap) * CO + co0 + c4 * 4];
            *(float4*)&s_w[ci][tap][c4 * 4] = v;
        }
        __syncthreads();
        #pragma unroll 1
        for (int ci = 0; ci < CICH; ci++) {
            unsigned long long vv[2][4];
            #pragma unroll
            for (int k = 0; k < 2; k++) {
                const int cell = px_id + k * 32;
                const int cy = cell / TW, cx = cell % TW;
                vv[k][0] = pack2(s_in[ci][cy][cx]);
                vv[k][1] = pack2(s_in[ci][cy][cx + 1]);
                vv[k][2] = pack2(s_in[ci][cy + 1][cx]);
                vv[k][3] = pack2(s_in[ci][cy + 1][cx + 1]);
            }
            #pragma unroll
            for (int tap = 0; tap < 9; tap++) {
                ulonglong2 wa = *(const ulonglong2*)&s_w[ci][tap][co_grp * 8];
                ulonglong2 wb = *(const ulonglong2*)&s_w[ci][tap][co_grp * 8 + 4];
                const int q = OUTI[tap], vi = VI[tap];
                #pragma unroll
                for (int k = 0; k < 2; k++) {
                    fma2(acc[0][k][q], wa.x, vv[k][vi]);
                    fma2(acc[1][k][q], wa.y, vv[k][vi]);
                    fma2(acc[2][k][q], wb.x, vv[k][vi]);
                    fma2(acc[3][k][q], wb.y, vv[k][vi]);
                }
            }
        }
        __syncthreads();
    }

    #pragma unroll
    for (int p = 0; p < 4; p++) {
        const int co = co0 + co_grp * 8 + 2 * p;
        #pragma unroll
        for (int k = 0; k < 2; k++) {
            const int cell = px_id + k * 32;
            const int gi = i0 + cell / TW, gj = j0 + cell % TW;
            const size_t base = (((size_t)n * CO + co) * HOUT + 2 * gi) * WOUT + 2 * gj;
            const size_t plane = (size_t)HOUT * WOUT;
            const size_t offs[4] = {0, 1, (size_t)WOUT, (size_t)WOUT + 1};
            #pragma unroll
            for (int q = 0; q < 4; q++) {
                float v0 = lo32(acc[p][k][q]), v1 = hi32(acc[p][k][q]);
                if constexpr (FUSE) {
                    v0 += bias[co]; v1 += bias[co + 1];
                    out[base + offs[q]] = LRELU(v0);
                    out[base + offs[q] + plane] = LRELU(v1);
                } else {
                    atomicAdd(&out[base + offs[q]], v0);
                    atomicAdd(&out[base + offs[q] + plane], v1);
                }
            }
        }
    }
}

// ---------------- dec4 (64->64 @256^2) fused with 1x1 epilogue 64->3 --------
__global__ __launch_bounds__(256, 2)
void conv_dec4_ep(const float* __restrict__ in, const float* __restrict__ wT,
                  const float* __restrict__ bias, const float* __restrict__ wep,
                  const float* __restrict__ bep, float* __restrict__ out) {
    constexpr int CI = 64, CO = 64, HIN = 256, WIN = 256;
    constexpr int TH = 8, TW = 8, TCO = 64, CICH = 8;
    constexpr int TILESX = WIN / TW;
    constexpr int PH = TH + 1, PW = TW + 1;

    __shared__ __align__(16) float s_in[CICH][PH][PW];
    __shared__ __align__(16) float s_w[CICH][9][TCO];
    __shared__ __align__(16) float s_out[16][256];   // 16 co at a time
    __shared__ float s_ep[3][64];
    __shared__ float s_bep[3];

    const int tid = threadIdx.x;
    const int px_id = tid & 31;
    const int co_grp = tid >> 5;
    const int n = blockIdx.y;
    const int ty = blockIdx.x / TILESX;
    const int tx = blockIdx.x % TILESX;
    const int i0 = ty * TH, j0 = tx * TW;

    if (tid < 192) s_ep[tid / 64][tid % 64] = wep[tid];
    if (tid < 3) s_bep[tid] = bep[tid];

    unsigned long long acc[4][2][4];
    #pragma unroll
    for (int p = 0; p < 4; p++)
        #pragma unroll
        for (int k = 0; k < 2; k++)
            #pragma unroll
            for (int q = 0; q < 4; q++) acc[p][k][q] = 0ull;

    constexpr int OUTI[9] = {3, 2, 3, 1, 0, 1, 3, 2, 3};
    constexpr int VI[9]   = {0, 0, 1, 0, 0, 1, 2, 2, 3};

    for (int cc = 0; cc < CI; cc += CICH) {
        #pragma unroll 1
        for (int idx = tid; idx < CICH * PH * PW; idx += 256) {
            int ci = idx / (PH * PW);
            int rem = idx - ci * (PH * PW);
            int r = rem / PW, c = rem - r * PW;
            int gy = i0 + r, gx = j0 + c;
            float v = 0.f;
            if (gy < HIN && gx < WIN)
                v = in[(((size_t)n * CI + cc + ci) * HIN + gy) * WIN + gx];
            s_in[ci][r][c] = v;
        }
        #pragma unroll 1
        for (int idx = tid; idx < CICH * 9 * (TCO / 4); idx += 256) {
            int row = idx / (TCO / 4);
            int c4 = idx - row * (TCO / 4);
            int ci = row / 9, tap = row - ci * 9;
            float4 v = *(const float4*)&wT[((size_t)(cc + ci) * 9 + tap) * CO + c4 * 4];
            *(float4*)&s_w[ci][tap][c4 * 4] = v;
        }
        __syncthreads();
        #pragma unroll 1
        for (int ci = 0; ci < CICH; ci++) {
            unsigned long long vv[2][4];
            #pragma unroll
            for (int k = 0; k < 2; k++) {
                const int cell = px_id + k * 32;
                const int cy = cell / TW, cx = cell % TW;
                vv[k][0] = pack2(s_in[ci][cy][cx]);
                vv[k][1] = pack2(s_in[ci][cy][cx + 1]);
                vv[k][2] = pack2(s_in[ci][cy + 1][cx]);
                vv[k][3] = pack2(s_in[ci][cy + 1][cx + 1]);
            }
            #pragma unroll
            for (int tap = 0; tap < 9; tap++) {
                ulonglong2 wa = *(const ulonglong2*)&s_w[ci][tap][co_grp * 8];
                ulonglong2 wb = *(const ulonglong2*)&s_w[ci][tap][co_grp * 8 + 4];
                const int q = OUTI[tap], vi = VI[tap];
                #pragma unroll
                for (int k = 0; k < 2; k++) {
                    fma2(acc[0][k][q], wa.x, vv[k][vi]);
                    fma2(acc[1][k][q], wa.y, vv[k][vi]);
                    fma2(acc[2][k][q], wb.x, vv[k][vi]);
                    fma2(acc[3][k][q], wb.y, vv[k][vi]);
                }
            }
        }
        __syncthreads();
    }

    // epilogue: stream activated outputs through smem 16 co at a time
    float a0 = s_bep[0], a1 = s_bep[1], a2 = s_bep[2];
    const int mycell = tid >> 2, myq = tid & 3;   // this thread's output pixel
    #pragma unroll 1
    for (int pp = 0; pp < 4; pp++) {
        if ((co_grp >> 1) == pp) {
            #pragma unroll
            for (int p = 0; p < 4; p++) {
                const int co = co_grp * 8 + 2 * p;
                const int cl = co - pp * 16;
                #pragma unroll
                for (int k = 0; k < 2; k++) {
                    const int cell = px_id + k * 32;
                    #pragma unroll
                    for (int q = 0; q < 4; q++) {
                        float v0 = lo32(acc[p][k][q]) + bias[co];
                        float v1 = hi32(acc[p][k][q]) + bias[co + 1];
                        s_out[cl][cell * 4 + q] = LRELU(v0);
                        s_out[cl + 1][cell * 4 + q] = LRELU(v1);
                    }
                }
            }
        }
        __syncthreads();
        #pragma unroll
        for (int cl = 0; cl < 16; cl++) {
            float v = s_out[cl][tid];
            int c = pp * 16 + cl;
            a0 += s_ep[0][c] * v;
            a1 += s_ep[1][c] * v;
            a2 += s_ep[2][c] * v;
        }
        __syncthreads();
    }

    const int gi = i0 + mycell / TW, gj = j0 + mycell % TW;
    const int gy = 2 * gi + (myq >> 1), gx = 2 * gj + (myq & 1);
    const size_t px = (size_t)gy * 512 + gx;
    out[((size_t)n * 3 + 0) * 262144 + px] = a0;
    out[((size_t)n * 3 + 1) * 262144 + px] = a1;
    out[((size_t)n * 3 + 2) * 262144 + px] = a2;
}

// ---------------- batchnorm stats on [2][1024][16][16] (raw conv sums) ------
__global__ void bn_stats_kernel(const float* __restrict__ h) {
    __shared__ float ssum[256], ssq[256];
    int c = blockIdx.x, tid = threadIdx.x;
    float v0 = h[((size_t)0 * 1024 + c) * 256 + tid];
    float v1 = h[((size_t)1 * 1024 + c) * 256 + tid];
    ssum[tid] = v0 + v1;
    ssq[tid] = v0 * v0 + v1 * v1;
    __syncthreads();
    for (int o = 128; o > 0; o >>= 1) {
        if (tid < o) { ssum[tid] += ssum[tid + o]; ssq[tid] += ssq[tid + o]; }
        __syncthreads();
    }
    if (tid == 0) {
        float m = ssum[0] * (1.f / 512.f);
        float var = ssq[0] * (1.f / 512.f) - m * m;
        g_mean[c] = m;
        g_invstd[c] = rsqrtf(var + 1e-5f);
    }
}

extern "C" void kernel_launch(void* const* d_in, const int* in_sizes, int n_in,
                              void* d_out, int out_size) {
    (void)in_sizes; (void)n_in; (void)out_size;
    float *bufA, *bufB, *wT;
    cudaGetSymbolAddress((void**)&bufA, g_bufA);
    cudaGetSymbolAddress((void**)&bufB, g_bufB);
    cudaGetSymbolAddress((void**)&wT, g_wT);

    const float* x    = (const float*)d_in[0];
    const float* w_d0 = (const float*)d_in[1];
    const float* b_d0 = (const float*)d_in[2];
    const float* w_d1 = (const float*)d_in[3];
    const float* b_d1 = (const float*)d_in[4];
    const float* w_d2 = (const float*)d_in[5];
    const float* b_d2 = (const float*)d_in[6];
    const float* w_d3 = (const float*)d_in[7];
    const float* b_d3 = (const float*)d_in[8];
    const float* w_d4 = (const float*)d_in[9];
    const float* b_d4 = (const float*)d_in[10];
    const float* w_in = (const float*)d_in[11];
    const float* gamma = (const float*)d_in[13];
    const float* beta  = (const float*)d_in[14];
    const float* w_u0 = (const float*)d_in[15];
    const float* b_u0 = (const float*)d_in[16];
    const float* w_u1 = (const float*)d_in[17];
    const float* b_u1 = (const float*)d_in[18];
    const float* w_u2 = (const float*)d_in[19];
    const float* b_u2 = (const float*)d_in[20];
    const float* w_u3 = (const float*)d_in[21];
    const float* b_u3 = (const float*)d_in[22];
    const float* w_u4 = (const float*)d_in[23];
    const float* b_u4 = (const float*)d_in[24];
    const float* w_ep = (const float*)d_in[25];
    const float* b_ep = (const float*)d_in[26];

    dim3 tb(32, 8);
    auto tg = [](int C, int R) { return dim3((unsigned)((C + 31) / 32), (unsigned)((R + 31) / 32)); };
    const float* np = nullptr;

    // launches 0..5 arranged so that ncu (-s 5 -c 1) profiles conv_enc2
    wtrans_kernel<<<tg(27, 64), tb>>>(w_d0, wT + OFF_D0, 64, 27);                       // 0
    conv_enc<3, 64, 256, 256, 2, 3, 1, true, M_NONE>
        <<<dim3(512, 2, 1), 256>>>(x, wT + OFF_D0, b_d0, np, np, np, bufA);             // 1
    wtrans_kernel<<<tg(576, 128), tb>>>(w_d1, wT + OFF_D1, 128, 576);                   // 2
    conv_enc<64, 128, 128, 128, 2, 8, 1, true, M_NONE>
        <<<dim3(128, 4, 1), 256>>>(bufA, wT + OFF_D1, b_d1, np, np, np, bufB);          // 3
    wtrans_kernel<<<tg(1152, 256), tb>>>(w_d2, wT + OFF_D2, 256, 1152);                 // 4
    conv_enc<128, 256, 64, 64, 2, 8, 1, true, M_NONE>
        <<<dim3(32, 8, 1), 256>>>(bufB, wT + OFF_D2, b_d2, np, np, np, bufA);           // 5 (profiled)

    wtrans_kernel<<<tg(2304, 512), tb>>>(w_d3, wT + OFF_D3, 512, 2304);
    zero_kernel<<<4096, 256>>>(bufB, 1048576);
    conv_enc<256, 512, 32, 32, 2, 8, 2, false, M_NONE>
        <<<dim3(8, 16, 2), 256>>>(bufA, wT + OFF_D3, np, np, np, np, bufB);             // raw sums

    wtrans_kernel<<<tg(4608, 1024), tb>>>(w_d4, wT + OFF_D4, 1024, 4608);
    zero_kernel<<<2048, 256>>>(bufA, 524288);
    conv_enc<512, 1024, 16, 16, 2, 8, 4, false, M_BIAS>
        <<<dim3(2, 32, 4), 256>>>(bufB, wT + OFF_D4, np, b_d3, np, np, bufA);           // raw sums

    wtrans_kernel<<<tg(9216, 1024), tb>>>(w_in, wT + OFF_IN, 1024, 9216);
    zero_kernel<<<2048, 256>>>(bufB, 524288);
    conv_enc<1024, 1024, 16, 16, 1, 8, 4, false, M_BIAS>
        <<<dim3(2, 32, 4), 256>>>(bufA, wT + OFF_IN, np, b_d4, np, np, bufB);           // raw sums
    bn_stats_kernel<<<1024, 256>>>(bufB);

    wtrans_kernel<<<tg(9216, 512), tb>>>(w_u0, wT + OFF_U0, 512, 9216);
    zero_kernel<<<4096, 256>>>(bufA, 1048576);
    conv_dec<1024, 512, 16, 16, 8, 4, false, M_BN>
        <<<dim3(4, 16, 4), 256>>>(bufB, wT + OFF_U0, np, np, gamma, beta, bufA);        // raw sums

    wtrans_kernel<<<tg(4608, 256), tb>>>(w_u1, wT + OFF_U1, 256, 4608);
    zero_kernel<<<8192, 256>>>(bufB, 2097152);
    conv_dec<512, 256, 32, 32, 8, 2, false, M_BIAS>
        <<<dim3(16, 8, 2), 256>>>(bufA, wT + OFF_U1, np, b_u0, np, np, bufB);           // raw sums

    wtrans_kernel<<<tg(2304, 128), tb>>>(w_u2, wT + OFF_U2, 128, 2304);
    conv_dec<256, 128, 64, 64, 8, 1, true, M_BIAS>
        <<<dim3(64, 4, 1), 256>>>(bufB, wT + OFF_U2, b_u2, b_u1, np, np, bufA);

    wtrans_kernel<<<tg(1152, 64), tb>>>(w_u3, wT + OFF_U3, 64, 1152);
    conv_dec<128, 64, 128, 128, 8, 1, true, M_NONE>
        <<<dim3(256, 2, 1), 256>>>(bufA, wT + OFF_U3, b_u3, np, np, np, bufB);

    wtrans_kernel<<<tg(576, 64), tb>>>(w_u4, wT + OFF_U4, 64, 576);
    conv_dec4_ep<<<dim3(1024, 2, 1), 256>>>(bufB, wT + OFF_U4, b_u4, w_ep, b_ep,
                                            (float*)d_out);
}

// round 6
// speedup vs baseline: 1.2448x; 1.2315x over previous
#include <cuda_runtime.h>
#include <cstdint>
#include <cstddef>

#define LRELU(v) ((v) >= 0.f ? (v) : 0.01f * (v))

static __device__ __forceinline__ void fma2(unsigned long long& acc,
                                            unsigned long long w,
                                            unsigned long long v) {
    asm("fma.rn.f32x2 %0, %1, %2, %0;" : "+l"(acc) : "l"(w), "l"(v));
}
static __device__ __forceinline__ unsigned long long pack2(float v) {
    unsigned long long r;
    asm("mov.b64 %0, {%1, %1};" : "=l"(r) : "f"(v));
    return r;
}
static __device__ __forceinline__ float lo32(unsigned long long a) {
    return __uint_as_float((unsigned)(a & 0xffffffffull));
}
static __device__ __forceinline__ float hi32(unsigned long long a) {
    return __uint_as_float((unsigned)(a >> 32));
}
static __device__ __forceinline__ unsigned smem_u32(const void* p) {
    return (unsigned)__cvta_generic_to_shared(p);
}
static __device__ __forceinline__ void cp4(unsigned dst, const float* src, bool ok) {
    asm volatile("cp.async.ca.shared.global [%0], [%1], 4, %2;"
                 :: "r"(dst), "l"(src), "r"(ok ? 4 : 0));
}
static __device__ __forceinline__ void cp16(unsigned dst, const float* src) {
    asm volatile("cp.async.cg.shared.global [%0], [%1], 16;" :: "r"(dst), "l"(src));
}
#define CP_COMMIT asm volatile("cp.async.commit_group;")
#define CP_WAIT1  asm volatile("cp.async.wait_group 1;")

__device__ __align__(16) float g_bufA[33554432];
__device__ __align__(16) float g_bufB[33554432];
__device__ __align__(16) float g_wT[22009536];
__device__ float g_mean[1024];
__device__ float g_invstd[1024];

#define OFF_D0 0
#define OFF_D1 1728
#define OFF_D2 75456
#define OFF_D3 370368
#define OFF_D4 1550016
#define OFF_IN 6268608
#define OFF_U0 15705792
#define OFF_U1 20424384
#define OFF_U2 21604032
#define OFF_U3 21898944
#define OFF_U4 21972672

// src [R=CO][C=CI*9] -> dst [C][R]
__global__ void wtrans_kernel(const float* __restrict__ src, float* __restrict__ dst,
                              int R, int C) {
    __shared__ float t[32][33];
    int bc = blockIdx.x * 32, br = blockIdx.y * 32;
    int x = threadIdx.x, y = threadIdx.y;
    #pragma unroll
    for (int j = 0; j < 32; j += 8) {
        int r = br + y + j, c = bc + x;
        if (r < R && c < C) t[y + j][x] = src[(size_t)r * C + c];
    }
    __syncthreads();
    #pragma unroll
    for (int j = 0; j < 32; j += 8) {
        int c = bc + y + j, r = br + x;
        if (r < R && c < C) dst[(size_t)c * R + r] = t[x][y + j];
    }
}

__global__ void zero_kernel(float* __restrict__ p, int n) {
    int i = blockIdx.x * 256 + threadIdx.x;
    if (i < n) p[i] = 0.f;
}

__global__ void bias_lrelu_kernel(float* __restrict__ p, const float* __restrict__ b,
                                  int HW, int C, int total) {
    int i = blockIdx.x * 256 + threadIdx.x;
    if (i < total) {
        int c = (i / HW) % C;
        float v = p[i] + b[c];
        p[i] = LRELU(v);
    }
}

// ---------------- encoder / plain conv (S=2 fused subsample) ----------------
template <int CI, int CO, int HO, int WO, int S, int CICH, int SPLIT>
__global__ __launch_bounds__(256, 2)
void conv_enc(const float* __restrict__ in, const float* __restrict__ wT,
              const float* __restrict__ bias, float* __restrict__ out, int fuse) {
    constexpr int TH = 8, TW = 16, TCO = 64;
    constexpr int HIN = HO * S, WIN = WO * S;
    constexpr int TILESX = WO / TW;
    constexpr int COT = CO / TCO;
    constexpr int PH = S * TH + 3 - S, PW = S * TW + 3 - S;
    constexpr int CIS = CI / SPLIT;
    constexpr int NCH = CIS / CICH;
    constexpr int INSZ = CICH * PH * PW;
    constexpr int WSZ = CICH * 9 * TCO;

    __shared__ __align__(16) float s_in[2][CICH][PH][PW];
    __shared__ __align__(16) float s_w[2][CICH][9][TCO];

    const int tid = threadIdx.x;
    const int px_id = tid & 31;
    const int co_grp = tid >> 5;
    const int n = blockIdx.y / COT;
    const int cot = blockIdx.y % COT;
    const int ty = blockIdx.x / TILESX;
    const int tx = blockIdx.x % TILESX;
    const int co0 = cot * TCO;
    const int oy0 = ty * TH, ox0 = tx * TW;
    const int iy0 = S * oy0 - 1, ix0 = S * ox0 - 1;
    const int ci_beg = CIS * blockIdx.z;
    const unsigned sb_in = smem_u32(&s_in[0][0][0][0]);
    const unsigned sb_w = smem_u32(&s_w[0][0][0][0]);

    auto load = [&](int cc, int b) {
        const int ci0 = ci_beg + cc * CICH;
        #pragma unroll 1
        for (int idx = tid; idx < INSZ; idx += 256) {
            int ci = idx / (PH * PW);
            int rem = idx - ci * (PH * PW);
            int r = rem / PW, c = rem - r * PW;
            int gy = iy0 + r, gx = ix0 + c;
            bool ok = (gy >= 0 && gy < HIN && gx >= 0 && gx < WIN);
            const float* src = ok ? &in[(((size_t)n * CI + ci0 + ci) * HIN + gy) * WIN + gx] : in;
            cp4(sb_in + (unsigned)(b * INSZ + idx) * 4u, src, ok);
        }
        #pragma unroll 1
        for (int idx = tid; idx < CICH * 9 * (TCO / 4); idx += 256) {
            int row = idx / (TCO / 4);
            int c4 = idx - row * (TCO / 4);
            int ci = row / 9, tap = row - ci * 9;
            cp16(sb_w + (unsigned)(b * WSZ + row * TCO + c4 * 4) * 4u,
                 &wT[((size_t)(ci0 + ci) * 9 + tap) * CO + co0 + c4 * 4]);
        }
    };

    unsigned long long acc[4][4];
    #pragma unroll
    for (int p = 0; p < 4; p++)
        #pragma unroll
        for (int k = 0; k < 4; k++) acc[p][k] = 0ull;

    load(0, 0);
    CP_COMMIT;
    #pragma unroll 1
    for (int cc = 0; cc < NCH; cc++) {
        const int b = cc & 1;
        if (cc + 1 < NCH) load(cc + 1, b ^ 1);
        CP_COMMIT;
        CP_WAIT1;
        __syncthreads();
        #pragma unroll 1
        for (int ci = 0; ci < CICH; ci++) {
            #pragma unroll
            for (int tap = 0; tap < 9; tap++) {
                const int ky = tap / 3, kx = tap % 3;
                ulonglong2 wa = *(const ulonglong2*)&s_w[b][ci][tap][co_grp * 8];
                ulonglong2 wb = *(const ulonglong2*)&s_w[b][ci][tap][co_grp * 8 + 4];
                #pragma unroll
                for (int k = 0; k < 4; k++) {
                    const int cell = px_id + k * 32;
                    const int cy = cell / TW, cx = cell % TW;
                    unsigned long long vv = pack2(s_in[b][ci][S * cy + ky][S * cx + kx]);
                    fma2(acc[0][k], wa.x, vv);
                    fma2(acc[1][k], wa.y, vv);
                    fma2(acc[2][k], wb.x, vv);
                    fma2(acc[3][k], wb.y, vv);
                }
            }
        }
        __syncthreads();
    }

    #pragma unroll
    for (int p = 0; p < 4; p++) {
        const int co = co0 + co_grp * 8 + 2 * p;
        #pragma unroll
        for (int k = 0; k < 4; k++) {
            const int cell = px_id + k * 32;
            const int cy = cell / TW, cx = cell % TW;
            const size_t idx = (((size_t)n * CO + co) * HO + oy0 + cy) * WO + ox0 + cx;
            float v0 = lo32(acc[p][k]), v1 = hi32(acc[p][k]);
            if (fuse) {
                v0 += bias[co]; v1 += bias[co + 1];
                out[idx] = LRELU(v0);
                out[idx + (size_t)HO * WO] = LRELU(v1);
            } else {
                atomicAdd(&out[idx], v0);
                atomicAdd(&out[idx + (size_t)HO * WO], v1);
            }
        }
    }
}

// ---------------- decoder: zero-insert up2 + conv3x3 ----------------
template <int CI, int CO, int HIN, int WIN, int CICH, int SPLIT>
__global__ __launch_bounds__(256, 2)
void conv_dec(const float* __restrict__ in, const float* __restrict__ wT,
              const float* __restrict__ bias, float* __restrict__ out, int fuse) {
    constexpr int TH = 8, TW = 8, TCO = 64;
    constexpr int HOUT = 2 * HIN, WOUT = 2 * WIN;
    constexpr int TILESX = WIN / TW;
    constexpr int COT = CO / TCO;
    constexpr int PH = TH + 1, PW = TW + 1;
    constexpr int CIS = CI / SPLIT;
    constexpr int NCH = CIS / CICH;
    constexpr int INSZ = CICH * PH * PW;
    constexpr int WSZ = CICH * 9 * TCO;

    __shared__ __align__(16) float s_in[2][CICH][PH][PW];
    __shared__ __align__(16) float s_w[2][CICH][9][TCO];

    const int tid = threadIdx.x;
    const int px_id = tid & 31;
    const int co_grp = tid >> 5;
    const int n = blockIdx.y / COT;
    const int cot = blockIdx.y % COT;
    const int ty = blockIdx.x / TILESX;
    const int tx = blockIdx.x % TILESX;
    const int co0 = cot * TCO;
    const int i0 = ty * TH, j0 = tx * TW;
    const int ci_beg = CIS * blockIdx.z;
    const unsigned sb_in = smem_u32(&s_in[0][0][0][0]);
    const unsigned sb_w = smem_u32(&s_w[0][0][0][0]);

    auto load = [&](int cc, int b) {
        const int ci0 = ci_beg + cc * CICH;
        #pragma unroll 1
        for (int idx = tid; idx < INSZ; idx += 256) {
            int ci = idx / (PH * PW);
            int rem = idx - ci * (PH * PW);
            int r = rem / PW, c = rem - r * PW;
            int gy = i0 + r, gx = j0 + c;
            bool ok = (gy < HIN && gx < WIN);
            const float* src = ok ? &in[(((size_t)n * CI + ci0 + ci) * HIN + gy) * WIN + gx] : in;
            cp4(sb_in + (unsigned)(b * INSZ + idx) * 4u, src, ok);
        }
        #pragma unroll 1
        for (int idx = tid; idx < CICH * 9 * (TCO / 4); idx += 256) {
            int row = idx / (TCO / 4);
            int c4 = idx - row * (TCO / 4);
            int ci = row / 9, tap = row - ci * 9;
            cp16(sb_w + (unsigned)(b * WSZ + row * TCO + c4 * 4) * 4u,
                 &wT[((size_t)(ci0 + ci) * 9 + tap) * CO + co0 + c4 * 4]);
        }
    };

    unsigned long long acc[4][2][4];
    #pragma unroll
    for (int p = 0; p < 4; p++)
        #pragma unroll
        for (int k = 0; k < 2; k++)
            #pragma unroll
            for (int q = 0; q < 4; q++) acc[p][k][q] = 0ull;

    constexpr int OUTI[9] = {3, 2, 3, 1, 0, 1, 3, 2, 3};
    constexpr int VI[9]   = {0, 0, 1, 0, 0, 1, 2, 2, 3};

    load(0, 0);
    CP_COMMIT;
    #pragma unroll 1
    for (int cc = 0; cc < NCH; cc++) {
        const int b = cc & 1;
        if (cc + 1 < NCH) load(cc + 1, b ^ 1);
        CP_COMMIT;
        CP_WAIT1;
        __syncthreads();
        #pragma unroll 1
        for (int ci = 0; ci < CICH; ci++) {
            unsigned long long vv[2][4];
            #pragma unroll
            for (int k = 0; k < 2; k++) {
                const int cell = px_id + k * 32;
                const int cy = cell / TW, cx = cell % TW;
                vv[k][0] = pack2(s_in[b][ci][cy][cx]);
                vv[k][1] = pack2(s_in[b][ci][cy][cx + 1]);
                vv[k][2] = pack2(s_in[b][ci][cy + 1][cx]);
                vv[k][3] = pack2(s_in[b][ci][cy + 1][cx + 1]);
            }
            #pragma unroll
            for (int tap = 0; tap < 9; tap++) {
                ulonglong2 wa = *(const ulonglong2*)&s_w[b][ci][tap][co_grp * 8];
                ulonglong2 wb = *(const ulonglong2*)&s_w[b][ci][tap][co_grp * 8 + 4];
                const int q = OUTI[tap], vi = VI[tap];
                #pragma unroll
                for (int k = 0; k < 2; k++) {
                    fma2(acc[0][k][q], wa.x, vv[k][vi]);
                    fma2(acc[1][k][q], wa.y, vv[k][vi]);
                    fma2(acc[2][k][q], wb.x, vv[k][vi]);
                    fma2(acc[3][k][q], wb.y, vv[k][vi]);
                }
            }
        }
        __syncthreads();
    }

    #pragma unroll
    for (int p = 0; p < 4; p++) {
        const int co = co0 + co_grp * 8 + 2 * p;
        #pragma unroll
        for (int k = 0; k < 2; k++) {
            const int cell = px_id + k * 32;
            const int gi = i0 + cell / TW, gj = j0 + cell % TW;
            const size_t base = (((size_t)n * CO + co) * HOUT + 2 * gi) * WOUT + 2 * gj;
            const size_t plane = (size_t)HOUT * WOUT;
            const size_t offs[4] = {0, 1, (size_t)WOUT, (size_t)WOUT + 1};
            #pragma unroll
            for (int q = 0; q < 4; q++) {
                float v0 = lo32(acc[p][k][q]), v1 = hi32(acc[p][k][q]);
                if (fuse) {
                    v0 += bias[co]; v1 += bias[co + 1];
                    out[base + offs[q]] = LRELU(v0);
                    out[base + offs[q] + plane] = LRELU(v1);
                } else {
                    atomicAdd(&out[base + offs[q]], v0);
                    atomicAdd(&out[base + offs[q] + plane], v1);
                }
            }
        }
    }
}

// ---------------- dec4 (64->64 @256^2) fused with 1x1 epilogue 64->3 --------
__global__ __launch_bounds__(256, 2)
void conv_dec4_ep(const float* __restrict__ in, const float* __restrict__ wT,
                  const float* __restrict__ bias, const float* __restrict__ wep,
                  const float* __restrict__ bep, float* __restrict__ out) {
    constexpr int CI = 64, CO = 64, HIN = 256, WIN = 256;
    constexpr int TH = 8, TW = 8, TCO = 64, CICH = 4;
    constexpr int TILESX = WIN / TW;
    constexpr int PH = TH + 1, PW = TW + 1;
    constexpr int NCH = CI / CICH;
    constexpr int INSZ = CICH * PH * PW;
    constexpr int WSZ = CICH * 9 * TCO;

    __shared__ __align__(16) float s_in[2][CICH][PH][PW];
    __shared__ __align__(16) float s_w[2][CICH][9][TCO];
    __shared__ __align__(16) float s_out[16][256];
    __shared__ float s_ep[3][64];
    __shared__ float s_bep[3];

    const int tid = threadIdx.x;
    const int px_id = tid & 31;
    const int co_grp = tid >> 5;
    const int n = blockIdx.y;
    const int ty = blockIdx.x / TILESX;
    const int tx = blockIdx.x % TILESX;
    const int i0 = ty * TH, j0 = tx * TW;
    const unsigned sb_in = smem_u32(&s_in[0][0][0][0]);
    const unsigned sb_w = smem_u32(&s_w[0][0][0][0]);

    if (tid < 192) s_ep[tid / 64][tid % 64] = wep[tid];
    if (tid < 3) s_bep[tid] = bep[tid];

    auto load = [&](int cc, int b) {
        const int ci0 = cc * CICH;
        #pragma unroll 1
        for (int idx = tid; idx < INSZ; idx += 256) {
            int ci = idx / (PH * PW);
            int rem = idx - ci * (PH * PW);
            int r = rem / PW, c = rem - r * PW;
            int gy = i0 + r, gx = j0 + c;
            bool ok = (gy < HIN && gx < WIN);
            const float* src = ok ? &in[(((size_t)n * CI + ci0 + ci) * HIN + gy) * WIN + gx] : in;
            cp4(sb_in + (unsigned)(b * INSZ + idx) * 4u, src, ok);
        }
        #pragma unroll 1
        for (int idx = tid; idx < CICH * 9 * (TCO / 4); idx += 256) {
            int row = idx / (TCO / 4);
            int c4 = idx - row * (TCO / 4);
            int ci = row / 9, tap = row - ci * 9;
            cp16(sb_w + (unsigned)(b * WSZ + row * TCO + c4 * 4) * 4u,
                 &wT[((size_t)(ci0 + ci) * 9 + tap) * CO + c4 * 4]);
        }
    };

    unsigned long long acc[4][2][4];
    #pragma unroll
    for (int p = 0; p < 4; p++)
        #pragma unroll
        for (int k = 0; k < 2; k++)
            #pragma unroll
            for (int q = 0; q < 4; q++) acc[p][k][q] = 0ull;

    constexpr int OUTI[9] = {3, 2, 3, 1, 0, 1, 3, 2, 3};
    constexpr int VI[9]   = {0, 0, 1, 0, 0, 1, 2, 2, 3};

    load(0, 0);
    CP_COMMIT;
    #pragma unroll 1
    for (int cc = 0; cc < NCH; cc++) {
        const int b = cc & 1;
        if (cc + 1 < NCH) load(cc + 1, b ^ 1);
        CP_COMMIT;
        CP_WAIT1;
        __syncthreads();
        #pragma unroll 1
        for (int ci = 0; ci < CICH; ci++) {
            unsigned long long vv[2][4];
            #pragma unroll
            for (int k = 0; k < 2; k++) {
                const int cell = px_id + k * 32;
                const int cy = cell / TW, cx = cell % TW;
                vv[k][0] = pack2(s_in[b][ci][cy][cx]);
                vv[k][1] = pack2(s_in[b][ci][cy][cx + 1]);
                vv[k][2] = pack2(s_in[b][ci][cy + 1][cx]);
                vv[k][3] = pack2(s_in[b][ci][cy + 1][cx + 1]);
            }
            #pragma unroll
            for (int tap = 0; tap < 9; tap++) {
                ulonglong2 wa = *(const ulonglong2*)&s_w[b][ci][tap][co_grp * 8];
                ulonglong2 wb = *(const ulonglong2*)&s_w[b][ci][tap][co_grp * 8 + 4];
                const int q = OUTI[tap], vi = VI[tap];
                #pragma unroll
                for (int k = 0; k < 2; k++) {
                    fma2(acc[0][k][q], wa.x, vv[k][vi]);
                    fma2(acc[1][k][q], wa.y, vv[k][vi]);
                    fma2(acc[2][k][q], wb.x, vv[k][vi]);
                    fma2(acc[3][k][q], wb.y, vv[k][vi]);
                }
            }
        }
        __syncthreads();
    }

    float a0 = s_bep[0], a1 = s_bep[1], a2 = s_bep[2];
    const int mycell = tid >> 2, myq = tid & 3;
    #pragma unroll 1
    for (int pp = 0; pp < 4; pp++) {
        if ((co_grp >> 1) == pp) {
            #pragma unroll
            for (int p = 0; p < 4; p++) {
                const int co = co_grp * 8 + 2 * p;
                const int cl = co - pp * 16;
                #pragma unroll
                for (int k = 0; k < 2; k++) {
                    const int cell = px_id + k * 32;
                    #pragma unroll
                    for (int q = 0; q < 4; q++) {
                        float v0 = lo32(acc[p][k][q]) + bias[co];
                        float v1 = hi32(acc[p][k][q]) + bias[co + 1];
                        s_out[cl][cell * 4 + q] = LRELU(v0);
                        s_out[cl + 1][cell * 4 + q] = LRELU(v1);
                    }
                }
            }
        }
        __syncthreads();
        #pragma unroll
        for (int cl = 0; cl < 16; cl++) {
            float v = s_out[cl][tid];
            int c = pp * 16 + cl;
            a0 += s_ep[0][c] * v;
            a1 += s_ep[1][c] * v;
            a2 += s_ep[2][c] * v;
        }
        __syncthreads();
    }

    const int gi = i0 + mycell / TW, gj = j0 + mycell % TW;
    const int gy = 2 * gi + (myq >> 1), gx = 2 * gj + (myq & 1);
    const size_t px = (size_t)gy * 512 + gx;
    out[((size_t)n * 3 + 0) * 262144 + px] = a0;
    out[((size_t)n * 3 + 1) * 262144 + px] = a1;
    out[((size_t)n * 3 + 2) * 262144 + px] = a2;
}

// ---------------- batchnorm on [2][1024][16][16] (raw conv sums) ------------
__global__ void bn_stats_kernel(const float* __restrict__ h) {
    __shared__ float ssum[256], ssq[256];
    int c = blockIdx.x, tid = threadIdx.x;
    float v0 = h[((size_t)0 * 1024 + c) * 256 + tid];
    float v1 = h[((size_t)1 * 1024 + c) * 256 + tid];
    ssum[tid] = v0 + v1;
    ssq[tid] = v0 * v0 + v1 * v1;
    __syncthreads();
    for (int o = 128; o > 0; o >>= 1) {
        if (tid < o) { ssum[tid] += ssum[tid + o]; ssq[tid] += ssq[tid + o]; }
        __syncthreads();
    }
    if (tid == 0) {
        float m = ssum[0] * (1.f / 512.f);
        float var = ssq[0] * (1.f / 512.f) - m * m;
        g_mean[c] = m;
        g_invstd[c] = rsqrtf(var + 1e-5f);
    }
}

__global__ void bn_apply_kernel(float* __restrict__ h, const float* __restrict__ gamma,
                                const float* __restrict__ beta) {
    int i = blockIdx.x * 256 + threadIdx.x;
    int c = (i >> 8) & 1023;
    float v = (h[i] - g_mean[c]) * g_invstd[c] * gamma[c] + beta[c];
    h[i] = LRELU(v);
}

extern "C" void kernel_launch(void* const* d_in, const int* in_sizes, int n_in,
                              void* d_out, int out_size) {
    (void)in_sizes; (void)n_in; (void)out_size;
    float *bufA, *bufB, *wT;
    cudaGetSymbolAddress((void**)&bufA, g_bufA);
    cudaGetSymbolAddress((void**)&bufB, g_bufB);
    cudaGetSymbolAddress((void**)&wT, g_wT);

    const float* x    = (const float*)d_in[0];
    const float* w_d0 = (const float*)d_in[1];
    const float* b_d0 = (const float*)d_in[2];
    const float* w_d1 = (const float*)d_in[3];
    const float* b_d1 = (const float*)d_in[4];
    const float* w_d2 = (const float*)d_in[5];
    const float* b_d2 = (const float*)d_in[6];
    const float* w_d3 = (const float*)d_in[7];
    const float* b_d3 = (const float*)d_in[8];
    const float* w_d4 = (const float*)d_in[9];
    const float* b_d4 = (const float*)d_in[10];
    const float* w_in = (const float*)d_in[11];
    const float* gamma = (const float*)d_in[13];
    const float* beta  = (const float*)d_in[14];
    const float* w_u0 = (const float*)d_in[15];
    const float* b_u0 = (const float*)d_in[16];
    const float* w_u1 = (const float*)d_in[17];
    const float* b_u1 = (const float*)d_in[18];
    const float* w_u2 = (const float*)d_in[19];
    const float* b_u2 = (const float*)d_in[20];
    const float* w_u3 = (const float*)d_in[21];
    const float* b_u3 = (const float*)d_in[22];
    const float* w_u4 = (const float*)d_in[23];
    const float* b_u4 = (const float*)d_in[24];
    const float* w_ep = (const float*)d_in[25];
    const float* b_ep = (const float*)d_in[26];

    dim3 tb(32, 8);
    auto tg = [](int C, int R) { return dim3((unsigned)((C + 31) / 32), (unsigned)((R + 31) / 32)); };

    // launches 0..5 kept identical in position so ncu profiles the same conv (enc1)
    wtrans_kernel<<<tg(27, 64), tb>>>(w_d0, wT + OFF_D0, 64, 27);                        // 0
    conv_enc<3, 64, 256, 256, 2, 3, 1>
        <<<dim3(512, 2, 1), 256>>>(x, wT + OFF_D0, b_d0, bufA, 1);                       // 1
    wtrans_kernel<<<tg(576, 128), tb>>>(w_d1, wT + OFF_D1, 128, 576);                    // 2
    conv_enc<64, 128, 128, 128, 2, 4, 1>
        <<<dim3(128, 4, 1), 256>>>(bufA, wT + OFF_D1, b_d1, bufB, 1);                    // 3 (profiled)
    wtrans_kernel<<<tg(1152, 256), tb>>>(w_d2, wT + OFF_D2, 256, 1152);                  // 4
    conv_enc<128, 256, 64, 64, 2, 4, 1>
        <<<dim3(32, 8, 1), 256>>>(bufB, wT + OFF_D2, b_d2, bufA, 1);                     // 5

    wtrans_kernel<<<tg(2304, 512), tb>>>(w_d3, wT + OFF_D3, 512, 2304);
    zero_kernel<<<4096, 256>>>(bufB, 1048576);
    conv_enc<256, 512, 32, 32, 2, 4, 2>
        <<<dim3(8, 16, 2), 256>>>(bufA, wT + OFF_D3, nullptr, bufB, 0);
    bias_lrelu_kernel<<<4096, 256>>>(bufB, b_d3, 1024, 512, 1048576);

    wtrans_kernel<<<tg(4608, 1024), tb>>>(w_d4, wT + OFF_D4, 1024, 4608);
    zero_kernel<<<2048, 256>>>(bufA, 524288);
    conv_enc<512, 1024, 16, 16, 2, 4, 4>
        <<<dim3(2, 32, 4), 256>>>(bufB, wT + OFF_D4, nullptr, bufA, 0);
    bias_lrelu_kernel<<<2048, 256>>>(bufA, b_d4, 256, 1024, 524288);

    wtrans_kernel<<<tg(9216, 1024), tb>>>(w_in, wT + OFF_IN, 1024, 9216);
    zero_kernel<<<2048, 256>>>(bufB, 524288);
    conv_enc<1024, 1024, 16, 16, 1, 4, 4>
        <<<dim3(2, 32, 4), 256>>>(bufA, wT + OFF_IN, nullptr, bufB, 0);
    bn_stats_kernel<<<1024, 256>>>(bufB);
    bn_apply_kernel<<<2048, 256>>>(bufB, gamma, beta);

    wtrans_kernel<<<tg(9216, 512), tb>>>(w_u0, wT + OFF_U0, 512, 9216);
    zero_kernel<<<4096, 256>>>(bufA, 1048576);
    conv_dec<1024, 512, 16, 16, 8, 4>
        <<<dim3(4, 16, 4), 256>>>(bufB, wT + OFF_U0, nullptr, bufA, 0);
    bias_lrelu_kernel<<<4096, 256>>>(bufA, b_u0, 1024, 512, 1048576);

    wtrans_kernel<<<tg(4608, 256), tb>>>(w_u1, wT + OFF_U1, 256, 4608);
    zero_kernel<<<8192, 256>>>(bufB, 2097152);
    conv_dec<512, 256, 32, 32, 8, 2>
        <<<dim3(16, 8, 2), 256>>>(bufA, wT + OFF_U1, nullptr, bufB, 0);
    bias_lrelu_kernel<<<8192, 256>>>(bufB, b_u1, 4096, 256, 2097152);

    wtrans_kernel<<<tg(2304, 128), tb>>>(w_u2, wT + OFF_U2, 128, 2304);
    conv_dec<256, 128, 64, 64, 8, 1>
        <<<dim3(64, 4, 1), 256>>>(bufB, wT + OFF_U2, b_u2, bufA, 1);

    wtrans_kernel<<<tg(1152, 64), tb>>>(w_u3, wT + OFF_U3, 64, 1152);
    conv_dec<128, 64, 128, 128, 8, 1>
        <<<dim3(256, 2, 1), 256>>>(bufA, wT + OFF_U3, b_u3, bufB, 1);

    wtrans_kernel<<<tg(576, 64), tb>>>(w_u4, wT + OFF_U4, 64, 576);
    conv_dec4_ep<<<dim3(1024, 2, 1), 256>>>(bufB, wT + OFF_U4, b_u4, w_ep, b_ep,
                                            (float*)d_out);
}